// round 8
// baseline (speedup 1.0000x reference)
#include <cuda_runtime.h>
#include <cstdint>

static constexpr int kNUsers = 100000;
static constexpr int kNItems = 500000;
static constexpr int kDim    = 64;
static constexpr int kNScore = 256;

static constexpr int ITILE  = 32;                    // items per tile (500000 % 32 == 0)
static constexpr int NTILES = kNItems / ITILE;       // 15625, exact
static constexpr int PITCH  = 68;                    // floats per row (64 + 4 pad) -> conflict-free

// ---- SMEM layout (float offsets) ----
static constexpr int OF_USQ = 0;                     // 256 floats
static constexpr int OF_ISQ = 256;                   // 32 floats
static constexpr int OF_U   = 288;                   // 256 * 68 = 17408 floats (startup only)
static constexpr int OF_I   = OF_U + 256 * PITCH;    // 17696
static constexpr int SMEM_FLOATS = OF_I + ITILE * PITCH;   // 19872
static constexpr unsigned SMEM_BYTES = SMEM_FLOATS * 4;    // 79488 B -> 2 CTAs/SM

__device__ __forceinline__ uint32_t f2tf32(float x) {
    uint32_t r;
    asm("cvt.rna.tf32.f32 %0, %1;" : "=r"(r) : "f"(x));
    return r;
}

__device__ __forceinline__ float rsum16(float sq) {
    sq += __shfl_xor_sync(0xffffffffu, sq, 1);
    sq += __shfl_xor_sync(0xffffffffu, sq, 2);
    sq += __shfl_xor_sync(0xffffffffu, sq, 4);
    sq += __shfl_xor_sync(0xffffffffu, sq, 8);
    return sq;
}

__global__ void __launch_bounds__(256, 2)
cml_kernel(const int* __restrict__ ids,
           const float* __restrict__ users,
           const float* __restrict__ items,
           float* __restrict__ out)
{
    extern __shared__ float smem[];
    float* usq = smem + OF_USQ;
    float* isq = smem + OF_ISQ;
    float* sU  = smem + OF_U;     // [256][PITCH] tf32 bits (used only for Bf init)
    float* sI  = smem + OF_I;     // [32][PITCH]  tf32 bits, item tile

    const int tid  = threadIdx.x;
    const int lane = tid & 31;
    const int w    = tid >> 5;    // warp id = user-slice id (32 users each)
    const int c    = tid & 15;    // float4 chunk within a 64-dim row
    const int r0   = tid >> 4;    // base row (16 rows per sweep)
    const int g    = lane >> 2;   // mma groupID
    const int t    = lane & 3;    // mma threadID-in-group

    // ---- stage all 256 users once: exact fp32 u_sq, rna-tf32 operand ----
    #pragma unroll
    for (int rr = 0; rr < 16; rr++) {
        const int r = r0 + rr * 16;
        const int uid = ids[r];
        float4 v = reinterpret_cast<const float4*>(users)[(size_t)uid * (kDim / 4) + c];
        float sq = rsum16(fmaf(v.x, v.x, fmaf(v.y, v.y, fmaf(v.z, v.z, v.w * v.w))));
        if (c == 0) usq[r] = sq;
        uint4 t4 = make_uint4(f2tf32(v.x), f2tf32(v.y), f2tf32(v.z), f2tf32(v.w));
        reinterpret_cast<uint4*>(sU + r * PITCH)[c] = t4;
    }
    __syncthreads();

    // ---- hoist this warp's B fragments (32 users x 64 k) into registers, forever ----
    uint32_t Bf[4][8][2];
    #pragma unroll
    for (int nb = 0; nb < 4; nb++) {
        #pragma unroll
        for (int kb = 0; kb < 8; kb++) {
            const uint32_t* bp = reinterpret_cast<const uint32_t*>(
                sU + (w * 32 + nb * 8 + g) * PITCH + kb * 8 + t);
            Bf[nb][kb][0] = bp[0];
            Bf[nb][kb][1] = bp[4];
        }
    }

    // ---- prefetch first item tile into registers ----
    const float4* items4 = reinterpret_cast<const float4*>(items);
    long tile = blockIdx.x;
    float4 pf0, pf1;
    if (tile < NTILES) {
        const long ib = tile * ITILE;
        pf0 = items4[(ib + r0) * 16 + c];
        pf1 = items4[(ib + r0 + 16) * 16 + c];
    }

    for (; tile < NTILES; tile += gridDim.x) {
        __syncthreads();   // all warps done reading sI/isq of previous tile

        // ---- commit prefetched tile: exact fp32 i_sq, rna-tf32 operand ----
        {
            const int r = r0;
            float sq = rsum16(fmaf(pf0.x, pf0.x, fmaf(pf0.y, pf0.y,
                              fmaf(pf0.z, pf0.z, pf0.w * pf0.w))));
            if (c == 0) isq[r] = sq;
            reinterpret_cast<uint4*>(sI + r * PITCH)[c] =
                make_uint4(f2tf32(pf0.x), f2tf32(pf0.y), f2tf32(pf0.z), f2tf32(pf0.w));
        }
        {
            const int r = r0 + 16;
            float sq = rsum16(fmaf(pf1.x, pf1.x, fmaf(pf1.y, pf1.y,
                              fmaf(pf1.z, pf1.z, pf1.w * pf1.w))));
            if (c == 0) isq[r] = sq;
            reinterpret_cast<uint4*>(sI + r * PITCH)[c] =
                make_uint4(f2tf32(pf1.x), f2tf32(pf1.y), f2tf32(pf1.z), f2tf32(pf1.w));
        }
        __syncthreads();

        // ---- issue next tile's loads now; hidden under the mma block below ----
        const long nt = tile + gridDim.x;
        if (nt < NTILES) {
            const long ib = nt * ITILE;
            pf0 = items4[(ib + r0) * 16 + c];
            pf1 = items4[(ib + r0 + 16) * 16 + c];
        }

        // ---- 32 items x 32 users per warp; A from SMEM, B from registers ----
        float acc[2][4][4];
        #pragma unroll
        for (int mb = 0; mb < 2; mb++)
            #pragma unroll
            for (int nb = 0; nb < 4; nb++)
                #pragma unroll
                for (int q = 0; q < 4; q++) acc[mb][nb][q] = 0.f;

        #pragma unroll
        for (int kb = 0; kb < 8; kb++) {
            uint32_t a[2][4];
            #pragma unroll
            for (int mb = 0; mb < 2; mb++) {
                const uint32_t* ap = reinterpret_cast<const uint32_t*>(
                    sI + (mb * 16 + g) * PITCH + kb * 8 + t);
                a[mb][0] = ap[0];
                a[mb][1] = ap[8 * PITCH];
                a[mb][2] = ap[4];
                a[mb][3] = ap[8 * PITCH + 4];
            }
            #pragma unroll
            for (int nb = 0; nb < 4; nb++) {
                #pragma unroll
                for (int mb = 0; mb < 2; mb++) {
                    asm volatile(
                        "mma.sync.aligned.m16n8k8.row.col.f32.tf32.tf32.f32 "
                        "{%0,%1,%2,%3}, {%4,%5,%6,%7}, {%8,%9}, {%0,%1,%2,%3};"
                        : "+f"(acc[mb][nb][0]), "+f"(acc[mb][nb][1]),
                          "+f"(acc[mb][nb][2]), "+f"(acc[mb][nb][3])
                        : "r"(a[mb][0]), "r"(a[mb][1]), "r"(a[mb][2]), "r"(a[mb][3]),
                          "r"(Bf[nb][kb][0]), "r"(Bf[nb][kb][1]));
                }
            }
        }

        // ---- epilogue: score = 2*cross - usq - isq (exact fp32 norms) ----
        const long ib = tile * ITILE;
        #pragma unroll
        for (int mb = 0; mb < 2; mb++) {
            const float is0 = isq[mb * 16 + g];
            const float is1 = isq[mb * 16 + g + 8];
            const long  i0  = ib + mb * 16 + g;
            #pragma unroll
            for (int nb = 0; nb < 4; nb++) {
                const float2 uq = *reinterpret_cast<const float2*>(
                    usq + w * 32 + nb * 8 + 2 * t);
                float* p0 = out + (size_t)(w * 32 + nb * 8 + 2 * t) * kNItems + i0;
                float* p1 = p0 + (size_t)kNItems;
                p0[0] = fmaf(2.f, acc[mb][nb][0], -(uq.x + is0));
                p1[0] = fmaf(2.f, acc[mb][nb][1], -(uq.y + is0));
                p0[8] = fmaf(2.f, acc[mb][nb][2], -(uq.x + is1));
                p1[8] = fmaf(2.f, acc[mb][nb][3], -(uq.y + is1));
            }
        }
    }
}

extern "C" void kernel_launch(void* const* d_in, const int* in_sizes, int n_in,
                              void* d_out, int out_size) {
    const int*   ids   = nullptr;
    const float* users = nullptr;
    const float* items = nullptr;
    for (int i = 0; i < n_in; i++) {
        if (in_sizes[i] == kNScore)              ids   = (const int*)d_in[i];
        else if (in_sizes[i] == kNUsers * kDim)  users = (const float*)d_in[i];
        else if (in_sizes[i] == kNItems * kDim)  items = (const float*)d_in[i];
    }
    cudaFuncSetAttribute(cml_kernel, cudaFuncAttributeMaxDynamicSharedMemorySize,
                         SMEM_BYTES);
    int sms = 0;
    if (cudaDeviceGetAttribute(&sms, cudaDevAttrMultiProcessorCount, 0) != cudaSuccess ||
        sms <= 0)
        sms = 148;
    cml_kernel<<<sms * 2, 256, SMEM_BYTES>>>(ids, users, items, (float*)d_out);
    (void)out_size;
}

// round 9
// speedup vs baseline: 1.2273x; 1.2273x over previous
#include <cuda_runtime.h>
#include <cstdint>

static constexpr int kNUsers = 100000;
static constexpr int kNItems = 500000;
static constexpr int kDim    = 64;
static constexpr int kNScore = 256;

static constexpr int ITILE  = 32;                    // 500000 % 32 == 0
static constexpr int NTILES = kNItems / ITILE;       // 15625 exact
static constexpr int PITCH  = 68;                    // floats per row; 272B = 16B-aligned rows

// ---- SMEM layout (float offsets) ----
static constexpr int OF_USQ = 0;                     // 256
static constexpr int OF_ISQ = 256;                   // 2 x 32 (double buffered)
static constexpr int OF_U   = 320;                   // 256*68 = 17408 (startup staging for Af/uq)
static constexpr int OF_I   = OF_U + 256 * PITCH;    // 17728; 2 x 32 x 68 = 4352
static constexpr int IBUF   = ITILE * PITCH;         // 2176 floats per item buffer
static constexpr int SMEM_FLOATS = OF_I + 2 * IBUF;  // 22080
static constexpr unsigned SMEM_BYTES = SMEM_FLOATS * 4;   // 88320 -> 2 CTAs/SM

__device__ __forceinline__ uint32_t f2tf32(float x) {
    uint32_t r;
    asm("cvt.rna.tf32.f32 %0, %1;" : "=r"(r) : "f"(x));
    return r;
}
__device__ __forceinline__ float rsum16(float sq) {
    sq += __shfl_xor_sync(0xffffffffu, sq, 1);
    sq += __shfl_xor_sync(0xffffffffu, sq, 2);
    sq += __shfl_xor_sync(0xffffffffu, sq, 4);
    sq += __shfl_xor_sync(0xffffffffu, sq, 8);
    return sq;
}

__global__ void __launch_bounds__(256, 2)
cml_kernel(const int* __restrict__ ids,
           const float* __restrict__ users,
           const float* __restrict__ items,
           float* __restrict__ out)
{
    extern __shared__ float smem[];
    float* usq = smem + OF_USQ;
    float* sU  = smem + OF_U;

    const int tid  = threadIdx.x;
    const int lane = tid & 31;
    const int w    = tid >> 5;    // warp id -> users w*32 .. w*32+31
    const int c    = tid & 15;    // float4 chunk within 64-dim row
    const int r0   = tid >> 4;    // staging row
    const int g    = lane >> 2;   // mma groupID
    const int t    = lane & 3;    // mma threadID-in-group
    const int uw   = w * 32;

    // ---- stage all 256 users: exact fp32 u_sq, rna-tf32 operand ----
    #pragma unroll
    for (int rr = 0; rr < 16; rr++) {
        const int r = r0 + rr * 16;
        const int uid = ids[r];
        float4 v = reinterpret_cast<const float4*>(users)[(size_t)uid * (kDim / 4) + c];
        float sq = rsum16(fmaf(v.x, v.x, fmaf(v.y, v.y, fmaf(v.z, v.z, v.w * v.w))));
        if (c == 0) usq[r] = sq;
        reinterpret_cast<uint4*>(sU + r * PITCH)[c] =
            make_uint4(f2tf32(v.x), f2tf32(v.y), f2tf32(v.z), f2tf32(v.w));
    }
    __syncthreads();

    // ---- hoist A fragments (this warp's 32 users, all k) into registers, forever ----
    // m16n8k8 row-major A: lane(g,t): a0=(g,t) a1=(g+8,t) a2=(g,t+4) a3=(g+8,t+4)
    uint32_t Af[2][8][4];
    #pragma unroll
    for (int mb = 0; mb < 2; mb++) {
        #pragma unroll
        for (int kb = 0; kb < 8; kb++) {
            const uint32_t* ap = reinterpret_cast<const uint32_t*>(
                sU + (uw + mb * 16 + g) * PITCH + kb * 8 + t);
            Af[mb][kb][0] = ap[0];
            Af[mb][kb][1] = ap[8 * PITCH];
            Af[mb][kb][2] = ap[4];
            Af[mb][kb][3] = ap[8 * PITCH + 4];
        }
    }
    // user norms for this thread's two rows per mb
    float uqr[2][2];
    #pragma unroll
    for (int mb = 0; mb < 2; mb++) {
        uqr[mb][0] = usq[uw + mb * 16 + g];
        uqr[mb][1] = usq[uw + mb * 16 + g + 8];
    }

    // per-thread B-fragment addressing: col j=g of block (p,h) holds item
    //   f = p*16 + 4*(g>>1) + 2h + (g&1); k-word swizzled by XOR 8 when (g>>2)&1
    const int iloc = 4 * (g >> 1) + (g & 1);          // item offset within (p,h) block
    const int sw8  = ((g >> 2) & 1) << 3;             // k-space XOR (32B) -> conflict-free banks

    const float4* items4 = reinterpret_cast<const float4*>(items);

    // ---- prefetch + stage first tile into buffer 0 ----
    long tile = blockIdx.x;
    {
        const long ib = tile * ITILE;
        float4 p0 = items4[(ib + r0) * 16 + c];
        float4 p1 = items4[(ib + r0 + 16) * 16 + c];
        float* sIb  = smem + OF_I;
        float* isqB = smem + OF_ISQ;
        {
            float sq = rsum16(fmaf(p0.x, p0.x, fmaf(p0.y, p0.y, fmaf(p0.z, p0.z, p0.w * p0.w))));
            if (c == 0) isqB[r0] = sq;
            const int cc = c ^ (((r0 >> 3) & 1) << 1);
            reinterpret_cast<uint4*>(sIb + r0 * PITCH)[cc] =
                make_uint4(f2tf32(p0.x), f2tf32(p0.y), f2tf32(p0.z), f2tf32(p0.w));
        }
        {
            const int r = r0 + 16;
            float sq = rsum16(fmaf(p1.x, p1.x, fmaf(p1.y, p1.y, fmaf(p1.z, p1.z, p1.w * p1.w))));
            if (c == 0) isqB[r] = sq;
            const int cc = c ^ (((r >> 3) & 1) << 1);
            reinterpret_cast<uint4*>(sIb + r * PITCH)[cc] =
                make_uint4(f2tf32(p1.x), f2tf32(p1.y), f2tf32(p1.z), f2tf32(p1.w));
        }
    }
    __syncthreads();

    int buf = 0;
    for (; tile < NTILES; tile += gridDim.x) {
        const long nt = tile + gridDim.x;

        // ---- issue next tile's LDGs now; consumed after compute ----
        float4 npf0, npf1;
        if (nt < NTILES) {
            const long ib = nt * ITILE;
            npf0 = items4[(ib + r0) * 16 + c];
            npf1 = items4[(ib + r0 + 16) * 16 + c];
        }

        float* sIb  = smem + OF_I + buf * IBUF;
        float* isqB = smem + OF_ISQ + buf * 32;

        // ---- 32 users x 32 items per warp; A regs, B smem (1 LDS.32 per mma) ----
        float acc[2][4][4];
        #pragma unroll
        for (int mb = 0; mb < 2; mb++)
            #pragma unroll
            for (int nb = 0; nb < 4; nb++)
                #pragma unroll
                for (int q = 0; q < 4; q++) acc[mb][nb][q] = 0.f;

        #pragma unroll
        for (int kb = 0; kb < 8; kb++) {
            #pragma unroll
            for (int p = 0; p < 2; p++) {
                #pragma unroll
                for (int h = 0; h < 2; h++) {
                    const int item = p * 16 + 2 * h + iloc;
                    const int kw   = (kb * 8 + t) ^ sw8;
                    const uint32_t* bp =
                        reinterpret_cast<const uint32_t*>(sIb + item * PITCH + kw);
                    const uint32_t b0 = bp[0];
                    const uint32_t b1 = bp[4];
                    #pragma unroll
                    for (int mb = 0; mb < 2; mb++) {
                        asm volatile(
                            "mma.sync.aligned.m16n8k8.row.col.f32.tf32.tf32.f32 "
                            "{%0,%1,%2,%3}, {%4,%5,%6,%7}, {%8,%9}, {%0,%1,%2,%3};"
                            : "+f"(acc[mb][2 * p + h][0]), "+f"(acc[mb][2 * p + h][1]),
                              "+f"(acc[mb][2 * p + h][2]), "+f"(acc[mb][2 * p + h][3])
                            : "r"(Af[mb][kb][0]), "r"(Af[mb][kb][1]),
                              "r"(Af[mb][kb][2]), "r"(Af[mb][kb][3]),
                              "r"(b0), "r"(b1));
                    }
                }
            }
        }

        // ---- epilogue: thread holds items 4t..4t+3 per user row -> STG.128 ----
        {
            const long ib = tile * ITILE;
            const float4 iqA = *reinterpret_cast<const float4*>(isqB + 4 * t);
            const float4 iqB4 = *reinterpret_cast<const float4*>(isqB + 16 + 4 * t);
            #pragma unroll
            for (int mb = 0; mb < 2; mb++) {
                float* base0 = out + (size_t)(uw + mb * 16 + g) * kNItems + ib + 4 * t;
                #pragma unroll
                for (int p = 0; p < 2; p++) {
                    const float4 iq = p ? iqB4 : iqA;
                    const float* a0 = acc[mb][2 * p];      // h=0: items 4t,4t+1
                    const float* a1 = acc[mb][2 * p + 1];  // h=1: items 4t+2,4t+3
                    float4 v;
                    v.x = fmaf(2.f, a0[0], -(uqr[mb][0] + iq.x));
                    v.y = fmaf(2.f, a0[1], -(uqr[mb][0] + iq.y));
                    v.z = fmaf(2.f, a1[0], -(uqr[mb][0] + iq.z));
                    v.w = fmaf(2.f, a1[1], -(uqr[mb][0] + iq.w));
                    *reinterpret_cast<float4*>(base0 + p * 16) = v;
                    float4 u;
                    u.x = fmaf(2.f, a0[2], -(uqr[mb][1] + iq.x));
                    u.y = fmaf(2.f, a0[3], -(uqr[mb][1] + iq.y));
                    u.z = fmaf(2.f, a1[2], -(uqr[mb][1] + iq.z));
                    u.w = fmaf(2.f, a1[3], -(uqr[mb][1] + iq.w));
                    *reinterpret_cast<float4*>(base0 + p * 16 + 8 * (size_t)kNItems) = u;
                }
            }
        }

        // ---- stage next tile into the other buffer; single sync per tile ----
        if (nt < NTILES) {
            float* sIn  = smem + OF_I + (buf ^ 1) * IBUF;
            float* isqN = smem + OF_ISQ + (buf ^ 1) * 32;
            {
                float sq = rsum16(fmaf(npf0.x, npf0.x, fmaf(npf0.y, npf0.y,
                                  fmaf(npf0.z, npf0.z, npf0.w * npf0.w))));
                if (c == 0) isqN[r0] = sq;
                const int cc = c ^ (((r0 >> 3) & 1) << 1);
                reinterpret_cast<uint4*>(sIn + r0 * PITCH)[cc] =
                    make_uint4(f2tf32(npf0.x), f2tf32(npf0.y), f2tf32(npf0.z), f2tf32(npf0.w));
            }
            {
                const int r = r0 + 16;
                float sq = rsum16(fmaf(npf1.x, npf1.x, fmaf(npf1.y, npf1.y,
                                  fmaf(npf1.z, npf1.z, npf1.w * npf1.w))));
                if (c == 0) isqN[r] = sq;
                const int cc = c ^ (((r >> 3) & 1) << 1);
                reinterpret_cast<uint4*>(sIn + r * PITCH)[cc] =
                    make_uint4(f2tf32(npf1.x), f2tf32(npf1.y), f2tf32(npf1.z), f2tf32(npf1.w));
            }
        }
        __syncthreads();
        buf ^= 1;
    }
}

extern "C" void kernel_launch(void* const* d_in, const int* in_sizes, int n_in,
                              void* d_out, int out_size) {
    const int*   ids   = nullptr;
    const float* users = nullptr;
    const float* items = nullptr;
    for (int i = 0; i < n_in; i++) {
        if (in_sizes[i] == kNScore)              ids   = (const int*)d_in[i];
        else if (in_sizes[i] == kNUsers * kDim)  users = (const float*)d_in[i];
        else if (in_sizes[i] == kNItems * kDim)  items = (const float*)d_in[i];
    }
    cudaFuncSetAttribute(cml_kernel, cudaFuncAttributeMaxDynamicSharedMemorySize,
                         SMEM_BYTES);
    int sms = 0;
    if (cudaDeviceGetAttribute(&sms, cudaDevAttrMultiProcessorCount, 0) != cudaSuccess ||
        sms <= 0)
        sms = 148;
    cml_kernel<<<sms * 2, 256, SMEM_BYTES>>>(ids, users, items, (float*)d_out);
    (void)out_size;
}

// round 11
// speedup vs baseline: 1.2415x; 1.0115x over previous
#include <cuda_runtime.h>
#include <cstdint>

static constexpr int kNUsers = 100000;
static constexpr int kNItems = 500000;
static constexpr int kDim    = 64;
static constexpr int kNScore = 256;

static constexpr int ITILE  = 32;                    // 500000 % 32 == 0
static constexpr int NTILES = kNItems / ITILE;       // 15625 exact
static constexpr int PITCH  = 68;                    // floats per row; 272 B, 16B-aligned

// ---- SMEM layout (float offsets) ----
static constexpr int OF_USQ = 0;                     // 256
static constexpr int OF_ISQ = 256;                   // 2 x 32 (double buffered)
static constexpr int OF_U   = 320;                   // 256*68 (startup staging)
static constexpr int OF_I   = OF_U + 256 * PITCH;    // 17728
static constexpr int IBUF   = ITILE * PITCH;         // 2176 floats per buffer
static constexpr int SMEM_FLOATS = OF_I + 2 * IBUF;  // 22080
static constexpr unsigned SMEM_BYTES = SMEM_FLOATS * 4;   // 88320 -> 2 CTAs/SM

__device__ __forceinline__ uint32_t smem_u32(const void* p) {
    return (uint32_t)__cvta_generic_to_shared(p);
}
__device__ __forceinline__ uint32_t f2tf32(float x) {
    uint32_t r;
    asm("cvt.rna.tf32.f32 %0, %1;" : "=r"(r) : "f"(x));
    return r;
}
__device__ __forceinline__ float rsum16(float sq) {
    sq += __shfl_xor_sync(0xffffffffu, sq, 1);
    sq += __shfl_xor_sync(0xffffffffu, sq, 2);
    sq += __shfl_xor_sync(0xffffffffu, sq, 4);
    sq += __shfl_xor_sync(0xffffffffu, sq, 8);
    return sq;
}
#define LDMX4(q, addr)                                                         \
    asm volatile("ldmatrix.sync.aligned.m8n8.x4.shared.b16 {%0,%1,%2,%3}, [%4];" \
                 : "=r"((q)[0]), "=r"((q)[1]), "=r"((q)[2]), "=r"((q)[3])      \
                 : "r"(addr))

__global__ void __launch_bounds__(256, 2)
cml_kernel(const int* __restrict__ ids,
           const float* __restrict__ users,
           const float* __restrict__ items,
           float* __restrict__ out)
{
    extern __shared__ float smem[];
    float* usq = smem + OF_USQ;
    float* sU  = smem + OF_U;

    const int tid  = threadIdx.x;
    const int lane = tid & 31;
    const int w    = tid >> 5;    // warp id -> users w*32 .. w*32+31
    const int c    = tid & 15;    // float4 chunk within 64-dim row
    const int r0   = tid >> 4;    // staging row
    const int g    = lane >> 2;   // mma groupID
    const int t    = lane & 3;    // mma threadID-in-group
    const int uw   = w * 32;

    // ---- stage all 256 users: exact fp32 u_sq, rna-tf32 operand ----
    #pragma unroll
    for (int rr = 0; rr < 16; rr++) {
        const int r = r0 + rr * 16;
        const int uid = ids[r];
        float4 v = reinterpret_cast<const float4*>(users)[(size_t)uid * (kDim / 4) + c];
        float sq = rsum16(fmaf(v.x, v.x, fmaf(v.y, v.y, fmaf(v.z, v.z, v.w * v.w))));
        if (c == 0) usq[r] = sq;
        reinterpret_cast<uint4*>(sU + r * PITCH)[c] =
            make_uint4(f2tf32(v.x), f2tf32(v.y), f2tf32(v.z), f2tf32(v.w));
    }
    __syncthreads();

    // ---- hoist A fragments (this warp's 32 users, all k) into registers, forever ----
    uint32_t Af[2][8][4];
    #pragma unroll
    for (int mb = 0; mb < 2; mb++) {
        #pragma unroll
        for (int kb = 0; kb < 8; kb++) {
            const uint32_t* ap = reinterpret_cast<const uint32_t*>(
                sU + (uw + mb * 16 + g) * PITCH + kb * 8 + t);
            Af[mb][kb][0] = ap[0];
            Af[mb][kb][1] = ap[8 * PITCH];
            Af[mb][kb][2] = ap[4];
            Af[mb][kb][3] = ap[8 * PITCH + 4];
        }
    }
    float uqr[2][2];
    #pragma unroll
    for (int mb = 0; mb < 2; mb++) {
        uqr[mb][0] = usq[uw + mb * 16 + g];
        uqr[mb][1] = usq[uw + mb * 16 + g + 8];
    }

    // ---- ldmatrix lane constants ----
    // For ldmatrix.x4, lane L supplies the row address of matrix (L>>3), row (L&7).
    // Matrix order per x4: m0=(h0,b0) m1=(h0,b1) m2=(h1,b0) m3=(h1,b1).
    // Permuted item for row r of (p,h): p*16 + 4*(r>>1) + 2h + (r&1)  (same f as epilogue).
    const int mtx   = lane >> 3;
    const int rrow  = lane & 7;
    const int h_l   = mtx >> 1;          // n-subblock (h)
    const int half  = mtx & 1;           // b0 / b1 (k-chunk half)
    const int item1 = 4 * (rrow >> 1) + 2 * h_l + (rrow & 1);     // p=0 item (0..15)
    const int xsw   = ((item1 >> 3) & 1) << 1;                    // staging chunk-XOR
    const uint32_t sbase     = smem_u32(smem);
    const uint32_t lanebase1 = (uint32_t)(OF_I * 4) + (uint32_t)item1 * (PITCH * 4);

    const float4* items4 = reinterpret_cast<const float4*>(items);

    // ---- prefetch + stage first tile into buffer 0 ----
    long tile = blockIdx.x;
    {
        const long ib = tile * ITILE;
        float4 p0 = __ldcs(&items4[(ib + r0) * 16 + c]);
        float4 p1 = __ldcs(&items4[(ib + r0 + 16) * 16 + c]);
        float* sIb  = smem + OF_I;
        float* isqB = smem + OF_ISQ;
        {
            float sq = rsum16(fmaf(p0.x, p0.x, fmaf(p0.y, p0.y, fmaf(p0.z, p0.z, p0.w * p0.w))));
            if (c == 0) isqB[r0] = sq;
            const int cc = c ^ (((r0 >> 3) & 1) << 1);
            reinterpret_cast<uint4*>(sIb + r0 * PITCH)[cc] =
                make_uint4(f2tf32(p0.x), f2tf32(p0.y), f2tf32(p0.z), f2tf32(p0.w));
        }
        {
            const int r = r0 + 16;
            float sq = rsum16(fmaf(p1.x, p1.x, fmaf(p1.y, p1.y, fmaf(p1.z, p1.z, p1.w * p1.w))));
            if (c == 0) isqB[r] = sq;
            const int cc = c ^ (((r >> 3) & 1) << 1);
            reinterpret_cast<uint4*>(sIb + r * PITCH)[cc] =
                make_uint4(f2tf32(p1.x), f2tf32(p1.y), f2tf32(p1.z), f2tf32(p1.w));
        }
    }
    __syncthreads();

    int buf = 0;
    for (; tile < NTILES; tile += gridDim.x) {
        const long nt = tile + gridDim.x;

        // ---- issue next tile's LDGs now; consumed after compute ----
        float4 npf0, npf1;
        if (nt < NTILES) {
            const long ib = nt * ITILE;
            npf0 = __ldcs(&items4[(ib + r0) * 16 + c]);
            npf1 = __ldcs(&items4[(ib + r0 + 16) * 16 + c]);
        }

        float* isqB = smem + OF_ISQ + buf * 32;
        const uint32_t sI_l1 = sbase + lanebase1 + (uint32_t)buf * (IBUF * 4);
        const uint32_t sI_l2 = sI_l1 + 16u * (PITCH * 4);    // p=1 items

        // ---- 32 users x 32 items per warp; A regs, B via ldmatrix.x4 ----
        float acc[2][4][4];
        #pragma unroll
        for (int mb = 0; mb < 2; mb++)
            #pragma unroll
            for (int nb = 0; nb < 4; nb++)
                #pragma unroll
                for (int q = 0; q < 4; q++) acc[mb][nb][q] = 0.f;

        #pragma unroll
        for (int kb = 0; kb < 8; kb++) {
            const uint32_t coff = (uint32_t)(((2 * kb + half) ^ xsw) * 16);
            uint32_t q[4];
            LDMX4(q, sI_l1 + coff);    // p=0: q0,q1 -> nb0 b0,b1 ; q2,q3 -> nb1
            #pragma unroll
            for (int mb = 0; mb < 2; mb++) {
                asm volatile(
                    "mma.sync.aligned.m16n8k8.row.col.f32.tf32.tf32.f32 "
                    "{%0,%1,%2,%3}, {%4,%5,%6,%7}, {%8,%9}, {%0,%1,%2,%3};"
                    : "+f"(acc[mb][0][0]), "+f"(acc[mb][0][1]),
                      "+f"(acc[mb][0][2]), "+f"(acc[mb][0][3])
                    : "r"(Af[mb][kb][0]), "r"(Af[mb][kb][1]),
                      "r"(Af[mb][kb][2]), "r"(Af[mb][kb][3]), "r"(q[0]), "r"(q[1]));
                asm volatile(
                    "mma.sync.aligned.m16n8k8.row.col.f32.tf32.tf32.f32 "
                    "{%0,%1,%2,%3}, {%4,%5,%6,%7}, {%8,%9}, {%0,%1,%2,%3};"
                    : "+f"(acc[mb][1][0]), "+f"(acc[mb][1][1]),
                      "+f"(acc[mb][1][2]), "+f"(acc[mb][1][3])
                    : "r"(Af[mb][kb][0]), "r"(Af[mb][kb][1]),
                      "r"(Af[mb][kb][2]), "r"(Af[mb][kb][3]), "r"(q[2]), "r"(q[3]));
            }
            uint32_t s[4];
            LDMX4(s, sI_l2 + coff);    // p=1: nb2, nb3
            #pragma unroll
            for (int mb = 0; mb < 2; mb++) {
                asm volatile(
                    "mma.sync.aligned.m16n8k8.row.col.f32.tf32.tf32.f32 "
                    "{%0,%1,%2,%3}, {%4,%5,%6,%7}, {%8,%9}, {%0,%1,%2,%3};"
                    : "+f"(acc[mb][2][0]), "+f"(acc[mb][2][1]),
                      "+f"(acc[mb][2][2]), "+f"(acc[mb][2][3])
                    : "r"(Af[mb][kb][0]), "r"(Af[mb][kb][1]),
                      "r"(Af[mb][kb][2]), "r"(Af[mb][kb][3]), "r"(s[0]), "r"(s[1]));
                asm volatile(
                    "mma.sync.aligned.m16n8k8.row.col.f32.tf32.tf32.f32 "
                    "{%0,%1,%2,%3}, {%4,%5,%6,%7}, {%8,%9}, {%0,%1,%2,%3};"
                    : "+f"(acc[mb][3][0]), "+f"(acc[mb][3][1]),
                      "+f"(acc[mb][3][2]), "+f"(acc[mb][3][3])
                    : "r"(Af[mb][kb][0]), "r"(Af[mb][kb][1]),
                      "r"(Af[mb][kb][2]), "r"(Af[mb][kb][3]), "r"(s[2]), "r"(s[3]));
            }
        }

        // ---- epilogue: thread holds items 4t..4t+3 per user row -> STG.128 (.cs) ----
        {
            const long ib = tile * ITILE;
            const float4 iqA  = *reinterpret_cast<const float4*>(isqB + 4 * t);
            const float4 iqB4 = *reinterpret_cast<const float4*>(isqB + 16 + 4 * t);
            #pragma unroll
            for (int mb = 0; mb < 2; mb++) {
                float* base0 = out + (size_t)(uw + mb * 16 + g) * kNItems + ib + 4 * t;
                #pragma unroll
                for (int p = 0; p < 2; p++) {
                    const float4 iq = p ? iqB4 : iqA;
                    const float* a0 = acc[mb][2 * p];      // h=0: items 4t,4t+1
                    const float* a1 = acc[mb][2 * p + 1];  // h=1: items 4t+2,4t+3
                    float4 v;
                    v.x = fmaf(2.f, a0[0], -(uqr[mb][0] + iq.x));
                    v.y = fmaf(2.f, a0[1], -(uqr[mb][0] + iq.y));
                    v.z = fmaf(2.f, a1[0], -(uqr[mb][0] + iq.z));
                    v.w = fmaf(2.f, a1[1], -(uqr[mb][0] + iq.w));
                    __stcs(reinterpret_cast<float4*>(base0 + p * 16), v);
                    float4 u;
                    u.x = fmaf(2.f, a0[2], -(uqr[mb][1] + iq.x));
                    u.y = fmaf(2.f, a0[3], -(uqr[mb][1] + iq.y));
                    u.z = fmaf(2.f, a1[2], -(uqr[mb][1] + iq.z));
                    u.w = fmaf(2.f, a1[3], -(uqr[mb][1] + iq.w));
                    __stcs(reinterpret_cast<float4*>(base0 + p * 16 + 8 * (size_t)kNItems), u);
                }
            }
        }

        // ---- stage next tile into the other buffer; single sync per tile ----
        if (nt < NTILES) {
            float* sIn  = smem + OF_I + (buf ^ 1) * IBUF;
            float* isqN = smem + OF_ISQ + (buf ^ 1) * 32;
            {
                float sq = rsum16(fmaf(npf0.x, npf0.x, fmaf(npf0.y, npf0.y,
                                  fmaf(npf0.z, npf0.z, npf0.w * npf0.w))));
                if (c == 0) isqN[r0] = sq;
                const int cc = c ^ (((r0 >> 3) & 1) << 1);
                reinterpret_cast<uint4*>(sIn + r0 * PITCH)[cc] =
                    make_uint4(f2tf32(npf0.x), f2tf32(npf0.y), f2tf32(npf0.z), f2tf32(npf0.w));
            }
            {
                const int r = r0 + 16;
                float sq = rsum16(fmaf(npf1.x, npf1.x, fmaf(npf1.y, npf1.y,
                                  fmaf(npf1.z, npf1.z, npf1.w * npf1.w))));
                if (c == 0) isqN[r] = sq;
                const int cc = c ^ (((r >> 3) & 1) << 1);
                reinterpret_cast<uint4*>(sIn + r * PITCH)[cc] =
                    make_uint4(f2tf32(npf1.x), f2tf32(npf1.y), f2tf32(npf1.z), f2tf32(npf1.w));
            }
        }
        __syncthreads();
        buf ^= 1;
    }
}

extern "C" void kernel_launch(void* const* d_in, const int* in_sizes, int n_in,
                              void* d_out, int out_size) {
    const int*   ids   = nullptr;
    const float* users = nullptr;
    const float* items = nullptr;
    for (int i = 0; i < n_in; i++) {
        if (in_sizes[i] == kNScore)              ids   = (const int*)d_in[i];
        else if (in_sizes[i] == kNUsers * kDim)  users = (const float*)d_in[i];
        else if (in_sizes[i] == kNItems * kDim)  items = (const float*)d_in[i];
    }
    cudaFuncSetAttribute(cml_kernel, cudaFuncAttributeMaxDynamicSharedMemorySize,
                         SMEM_BYTES);
    int sms = 0;
    if (cudaDeviceGetAttribute(&sms, cudaDevAttrMultiProcessorCount, 0) != cudaSuccess ||
        sms <= 0)
        sms = 148;
    cml_kernel<<<sms * 2, 256, SMEM_BYTES>>>(ids, users, items, (float*)d_out);
    (void)out_size;
}